// round 12
// baseline (speedup 1.0000x reference)
#include <cuda_runtime.h>
#include <cuda_bf16.h>

// Scratch (no allocations allowed -> __device__ globals)
__device__ float g_LU[2][128 * 128];     // LU factors of (I - A/2), row-major
__device__ float g_QT[2][128 * 128];     // QT[m][j*128+i] = Q[j][i]
__device__ float g_table[4096 * 128];    // pathemb table for every position value

// Inter-block phase counters, 128B apart. Zero at load; reset each call by the
// last block through the exit counter -> replay-safe.
__device__ volatile unsigned g_flags[4 * 32];  // [0]=c1 lu, [32]=c2 solve, [64]=c3 table, [96]=c4 exit

#define LU_PITCH 129
#define NBLOCKS  128
#define TBL_SMEM_FLOATS (2 * 16384 + 2 * 2048)   // 36864 floats = 144 KB

__device__ __forceinline__ void poll_ge(int idx, unsigned tgt) {
    while (g_flags[idx] < tgt) {}
}

// ---------------------------------------------------------------------------
// Single persistent kernel: LU (blk 0-1) -> solve (blk 0-15) -> table (all) ->
// global barrier -> output (all). 128 blocks, 1/SM (144KB smem), all resident.
// ---------------------------------------------------------------------------
__global__ __launch_bounds__(512, 1) void mega_kernel(const float* __restrict__ X,
                                                      const float* __restrict__ identity,
                                                      const int* __restrict__ tt,
                                                      const int* __restrict__ tv,
                                                      const int* __restrict__ np,
                                                      const float* __restrict__ ew,
                                                      float* __restrict__ out) {
    extern __shared__ float sm[];
    __shared__ float colbuf[2][128];
    __shared__ float rowbuf[2][128];
    __shared__ float pinvbuf[2];
    __shared__ int   pv[2][16];

    const int blk  = blockIdx.x;
    const int t    = threadIdx.x;
    const int tr   = t & 31;          // lane
    const int w    = t >> 5;          // warp id (0..15)
    const unsigned FULL = 0xffffffffu;

    // =========================== Phase 1: LU ===============================
    if (blk < 2) {
        const int m = blk;
        const float* Xm = X + m * 128 * 128;
        float* Xs = sm;                                  // 128*129

        for (int idx = t; idx < 128 * 128; idx += 512)
            Xs[(idx >> 7) * LU_PITCH + (idx & 127)] = Xm[idx];
        __syncthreads();

        float reg[4][8];
#pragma unroll
        for (int s = 0; s < 4; s++) {
            const int r = tr + 32 * s;
#pragma unroll
            for (int q = 0; q < 8; q++) {
                const int c = 8 * w + q;
                float a = (r > c) ? Xs[r * LU_PITCH + c]
                        : ((r < c) ? -Xs[c * LU_PITCH + r] : 0.0f);
                reg[s][q] = ((r == c) ? 1.0f : 0.0f) - 0.5f * a;
            }
        }
        if (w == 0) {
#pragma unroll
            for (int s = 0; s < 4; s++) colbuf[0][tr + 32 * s] = reg[s][0];
        }
        if (tr == 0) {
#pragma unroll
            for (int q = 0; q < 8; q++) rowbuf[0][8 * w + q] = reg[0][q];
            if (w == 0) pinvbuf[0] = 1.0f / reg[0][0];
        }

        for (int k = 0; k < 128; k++) {
            __syncthreads();
            const int p = k & 1;
            if (8 * w + 7 >= k) {                        // warp-uniform dead skip
                const float pinv = pinvbuf[p];
                float l[4];
#pragma unroll
                for (int s = 0; s < 4; s++) l[s] = colbuf[p][tr + 32 * s] * pinv;
                float rb[8];
#pragma unroll
                for (int q = 0; q < 8; q++) rb[q] = rowbuf[p][8 * w + q];
#pragma unroll
                for (int s = 0; s < 4; s++) {
                    const int r = tr + 32 * s;
                    const bool act = (r > k);
#pragma unroll
                    for (int q = 0; q < 8; q++) {
                        const int c = 8 * w + q;
                        if (act) {
                            if (c > k)       reg[s][q] -= l[s] * rb[q];
                            else if (c == k) reg[s][q]  = l[s];
                        }
                    }
                }
                if (k < 127) {
                    const int kn = k + 1;
                    if (w == (kn >> 3)) {
                        const int qn = kn & 7;
#pragma unroll
                        for (int s = 0; s < 4; s++) {
                            float v = reg[s][0];
#pragma unroll
                            for (int qq = 1; qq < 8; qq++)
                                if (qq == qn) v = reg[s][qq];
                            colbuf[p ^ 1][tr + 32 * s] = v;
                        }
                    }
                    if (tr == (kn & 31)) {
                        const int sn = kn >> 5;
                        float vr[8];
#pragma unroll
                        for (int q = 0; q < 8; q++) {
                            float v = reg[0][q];
#pragma unroll
                            for (int ss = 1; ss < 4; ss++)
                                if (ss == sn) v = reg[ss][q];
                            vr[q] = v;
                            rowbuf[p ^ 1][8 * w + q] = v;
                        }
                        if (w == (kn >> 3)) {
                            const int qn = kn & 7;
                            float v = vr[0];
#pragma unroll
                            for (int qq = 1; qq < 8; qq++)
                                if (qq == qn) v = vr[qq];
                            pinvbuf[p ^ 1] = 1.0f / v;
                        }
                    }
                }
            }
        }
        __syncthreads();
#pragma unroll
        for (int s = 0; s < 4; s++) {
            const int r = tr + 32 * s;
#pragma unroll
            for (int q = 0; q < 8; q++)
                Xs[r * LU_PITCH + 8 * w + q] = reg[s][q];
        }
        __syncthreads();
        for (int idx = t; idx < 128 * 128; idx += 512)
            g_LU[m][idx] = Xs[(idx >> 7) * LU_PITCH + (idx & 127)];
        __syncthreads();
        __threadfence();
        if (t == 0) atomicAdd((unsigned*)&g_flags[0], 1u);      // c1++
    }

    // =========================== Phase 2: solve =============================
    if (blk < 16) {
        if (t == 0) poll_ge(0, 2u);
        __syncthreads();
        __threadfence();

        const int m = blk >> 3;
        const int j = ((blk & 7) << 4) + w;              // 16 RHS per block
        const float* Xm  = X + m * 128 * 128;
        const float* LUg = g_LU[m];
        float* LUs   = sm;                               // 128*129
        float* rdiag = sm + 128 * LU_PITCH;              // 128

        for (int idx = t; idx < 128 * 128; idx += 512)
            LUs[(idx >> 7) * LU_PITCH + (idx & 127)] = LUg[idx];
        if (t < 128) rdiag[t] = 1.0f / LUg[t * 128 + t];
        __syncthreads();

        const int lane = tr;
        float y0, y1, y2, y3;
        {
            const int i0 = lane, i1 = lane + 32, i2 = lane + 64, i3 = lane + 96;
            float a0 = (i0 > j) ? Xm[i0 * 128 + j] : ((i0 < j) ? -Xm[j * 128 + i0] : 0.0f);
            float a1 = (i1 > j) ? Xm[i1 * 128 + j] : ((i1 < j) ? -Xm[j * 128 + i1] : 0.0f);
            float a2 = (i2 > j) ? Xm[i2 * 128 + j] : ((i2 < j) ? -Xm[j * 128 + i2] : 0.0f);
            float a3 = (i3 > j) ? Xm[i3 * 128 + j] : ((i3 < j) ? -Xm[j * 128 + i3] : 0.0f);
            y0 = ((i0 == j) ? 1.0f : 0.0f) + 0.5f * a0;
            y1 = ((i1 == j) ? 1.0f : 0.0f) + 0.5f * a1;
            y2 = ((i2 == j) ? 1.0f : 0.0f) + 0.5f * a2;
            y3 = ((i3 == j) ? 1.0f : 0.0f) + 0.5f * a3;
        }

        // forward: L z = r (unit lower)
#pragma unroll 4
        for (int kk = 0; kk < 32; kk++) {
            const float yk = __shfl_sync(FULL, y0, kk);
            const float* col = LUs + kk;
            if (lane > kk) y0 -= col[lane * LU_PITCH] * yk;
            y1 -= col[(lane + 32) * LU_PITCH] * yk;
            y2 -= col[(lane + 64) * LU_PITCH] * yk;
            y3 -= col[(lane + 96) * LU_PITCH] * yk;
        }
#pragma unroll 4
        for (int kk = 0; kk < 32; kk++) {
            const float yk = __shfl_sync(FULL, y1, kk);
            const float* col = LUs + 32 + kk;
            if (lane > kk) y1 -= col[(lane + 32) * LU_PITCH] * yk;
            y2 -= col[(lane + 64) * LU_PITCH] * yk;
            y3 -= col[(lane + 96) * LU_PITCH] * yk;
        }
#pragma unroll 4
        for (int kk = 0; kk < 32; kk++) {
            const float yk = __shfl_sync(FULL, y2, kk);
            const float* col = LUs + 64 + kk;
            if (lane > kk) y2 -= col[(lane + 64) * LU_PITCH] * yk;
            y3 -= col[(lane + 96) * LU_PITCH] * yk;
        }
#pragma unroll 4
        for (int kk = 0; kk < 31; kk++) {
            const float yk = __shfl_sync(FULL, y3, kk);
            if (lane > kk) y3 -= LUs[(lane + 96) * LU_PITCH + 96 + kk] * yk;
        }
        // backward: U q = z
#pragma unroll 4
        for (int kk = 31; kk >= 0; kk--) {
            const int k = 96 + kk;
            const float yk = __shfl_sync(FULL, y3, kk) * rdiag[k];
            if (lane == kk) y3 = yk;
            else if (lane < kk) y3 -= LUs[(lane + 96) * LU_PITCH + k] * yk;
            y0 -= LUs[lane * LU_PITCH + k] * yk;
            y1 -= LUs[(lane + 32) * LU_PITCH + k] * yk;
            y2 -= LUs[(lane + 64) * LU_PITCH + k] * yk;
        }
#pragma unroll 4
        for (int kk = 31; kk >= 0; kk--) {
            const int k = 64 + kk;
            const float yk = __shfl_sync(FULL, y2, kk) * rdiag[k];
            if (lane == kk) y2 = yk;
            else if (lane < kk) y2 -= LUs[(lane + 64) * LU_PITCH + k] * yk;
            y0 -= LUs[lane * LU_PITCH + k] * yk;
            y1 -= LUs[(lane + 32) * LU_PITCH + k] * yk;
        }
#pragma unroll 4
        for (int kk = 31; kk >= 0; kk--) {
            const int k = 32 + kk;
            const float yk = __shfl_sync(FULL, y1, kk) * rdiag[k];
            if (lane == kk) y1 = yk;
            else if (lane < kk) y1 -= LUs[(lane + 32) * LU_PITCH + k] * yk;
            y0 -= LUs[lane * LU_PITCH + k] * yk;
        }
#pragma unroll 4
        for (int kk = 31; kk >= 0; kk--) {
            const float yk = __shfl_sync(FULL, y0, kk) * rdiag[kk];
            if (lane == kk) y0 = yk;
            else if (lane < kk) y0 -= LUs[lane * LU_PITCH + kk] * yk;
        }
        float* dst = g_QT[m] + j * 128 + lane;
        dst[0] = y0; dst[32] = y1; dst[64] = y2; dst[96] = y3;

        __syncthreads();
        __threadfence();
        if (t == 0) atomicAdd((unsigned*)&g_flags[32], 1u);     // c2++
    }

    // =========================== Phase 3: table =============================
    if (t == 0) poll_ge(32, 16u);
    __syncthreads();
    __threadfence();

    {
        float* Q0s  = sm;
        float* Q1s  = sm + 16384;
        float* bufA = sm + 32768;
        float* bufB = sm + 34816;
        const int g = blk;
        const int l = t >> 7;
        const int j = t & 127;

        {
            const float4* src = (const float4*)g_QT;
            float4* dst = (float4*)sm;
            for (int i = t; i < 8192; i += 512) dst[i] = src[i];
        }
        if (t < 128) bufA[j] = identity[j];
        if (g == 0 && t < 128) {
            g_table[0 + j]   = identity[j];
            g_table[128 + j] = identity[j];
        }
        __syncthreads();

        float* cur = bufA;
        float* nxt = bufB;
        for (int d = 0; d < 7; d++) {                    // root path: levels 2..8
            if (t < 128) {
                const int b = (g >> d) & 1;
                const float* Qp = b ? Q1s : Q0s;
                float a0 = 0.f, a1 = 0.f, a2 = 0.f, a3 = 0.f;
                for (int i = 0; i < 128; i += 4) {
                    const float4 vv = *(const float4*)(cur + i);
                    a0 += vv.x * Qp[(i + 0) * 128 + j];
                    a1 += vv.y * Qp[(i + 1) * 128 + j];
                    a2 += vv.z * Qp[(i + 2) * 128 + j];
                    a3 += vv.w * Qp[(i + 3) * 128 + j];
                }
                const float acc = (a0 + a1) + (a2 + a3);
                nxt[j] = acc;
                const int p = (g & ((2 << d) - 1)) | (2 << d);
                g_table[p * 128 + j] = acc;
            }
            __syncthreads();
            float* tmp = cur; cur = nxt; nxt = tmp;
        }
        if (t == 0) pv[0][0] = 128 + g;
        __syncthreads();

        int cnt = 1, msb = 128, sel = 0;
        for (int lvl = 0; lvl < 4; lvl++) {              // levels 9..12
            const int nch = cnt * 2;
            for (int cb = 0; cb < nch; cb += 4) {
                const int c = cb + l;
                if (c < nch) {
                    const int par = c >> 1;
                    const int b   = c & 1;
                    const int pc  = pv[sel][par] + (b + 1) * msb;
                    const float* Qp = b ? Q1s : Q0s;
                    const float* vp = cur + par * 128;
                    float a0 = 0.f, a1 = 0.f, a2 = 0.f, a3 = 0.f;
                    for (int i = 0; i < 128; i += 4) {
                        const float4 vv = *(const float4*)(vp + i);
                        a0 += vv.x * Qp[(i + 0) * 128 + j];
                        a1 += vv.y * Qp[(i + 1) * 128 + j];
                        a2 += vv.z * Qp[(i + 2) * 128 + j];
                        a3 += vv.w * Qp[(i + 3) * 128 + j];
                    }
                    const float acc = (a0 + a1) + (a2 + a3);
                    nxt[c * 128 + j] = acc;
                    g_table[pc * 128 + j] = acc;
                    if (j == 0) pv[sel ^ 1][c] = pc;
                }
            }
            __syncthreads();
            float* tmp = cur; cur = nxt; nxt = tmp;
            sel ^= 1; cnt = nch; msb <<= 1;
        }
    }

    // ================== Global barrier: table complete ======================
    __syncthreads();
    __threadfence();
    if (t == 0) {
        atomicAdd((unsigned*)&g_flags[64], 1u);          // c3++
        poll_ge(64, (unsigned)NBLOCKS);
    }
    __syncthreads();
    __threadfence();

    // =========================== Phase 4: output ============================
    // 128 blocks x 16 warps x 64 tokens = 131072. Metadata loaded coalesced
    // (32 tokens/warp batch), broadcast per token via shfl -> warp-uniform
    // branches. 128 MB write -> HBM-bound; write-back stores let the L2 flush
    // overlap the next replay's compute phases.
    {
        const int tok0 = (blk << 10) + (w << 6);
#pragma unroll 1
        for (int half = 0; half < 2; half++) {
            const int tb   = tok0 + (half << 5);
            const int mty  = tt[tb + tr];
            const int mval = tv[tb + tr];
            const int mpos = np[tb + tr];
#pragma unroll 4
            for (int u = 0; u < 32; u++) {
                const int ty  = __shfl_sync(FULL, mty,  u);
                const int val = __shfl_sync(FULL, mval, u);
                const int pos = __shfl_sync(FULL, mpos, u);

                const float4 pv4 = *(const float4*)(g_table + pos * 128 + tr * 4);

                float4 cv;
                if (ty == 4) {
                    int idx = val < 0 ? 0 : (val > 4095 ? 4095 : val);
                    cv = *(const float4*)(g_table + idx * 128 + tr * 4);
                } else if (ty == 1) {
                    cv = *(const float4*)(ew + (val + 1) * 128 + tr * 4);
                } else if (ty == 2) {
                    cv = *(const float4*)(ew + (val + 5) * 128 + tr * 4);
                } else if (ty == 0) {
                    cv = *(const float4*)(ew + tr * 4);
                } else if (ty == 3 && val == -1) {
                    cv = *(const float4*)(ew + 10 * 128 + tr * 4);
                } else {
                    cv = make_float4(0.f, 0.f, 0.f, 0.f);
                }

                float* o = out + (size_t)(tb + u) * 256;
                *(float4*)(o + tr * 4)       = cv;
                *(float4*)(o + 128 + tr * 4) = pv4;
            }
        }
    }

    // ============ exit counter + replay-safe flag reset =====================
    __syncthreads();
    __threadfence();
    if (t == 0) {
        if (atomicAdd((unsigned*)&g_flags[96], 1u) == NBLOCKS - 1) {
            // every block has passed all polls (each incremented c4 after its
            // last poll) -> safe to zero the monotone counters for the next call
            g_flags[0]  = 0u;
            g_flags[32] = 0u;
            g_flags[64] = 0u;
            g_flags[96] = 0u;
            __threadfence();
        }
    }
}

// ---------------------------------------------------------------------------
extern "C" void kernel_launch(void* const* d_in, const int* in_sizes, int n_in,
                              void* d_out, int out_size) {
    const int*   tt    = (const int*)d_in[0];   // token_types   [32,4096]
    const int*   tv    = (const int*)d_in[1];   // token_values  [32,4096]
    const int*   np    = (const int*)d_in[2];   // node_positions[32,4096]
    const float* prim  = (const float*)d_in[3]; // primitives    [2,128,128]
    const float* ident = (const float*)d_in[4]; // identity      [1,128]
    const float* ew    = (const float*)d_in[5]; // embed_weight  [11,128]
    float* out = (float*)d_out;

    const int mega_smem = TBL_SMEM_FLOATS * (int)sizeof(float);   // 147456 B
    cudaFuncSetAttribute(mega_kernel, cudaFuncAttributeMaxDynamicSharedMemorySize, mega_smem);

    mega_kernel<<<NBLOCKS, 512, mega_smem>>>(prim, ident, tt, tv, np, ew, out);
}

// round 13
// speedup vs baseline: 1.4483x; 1.4483x over previous
#include <cuda_runtime.h>
#include <cuda_bf16.h>

// Scratch (no allocations allowed -> __device__ globals)
__device__ float g_LU[2][128 * 128];     // LU factors of (I - A/2), row-major
__device__ float g_QT[2][128 * 128];     // QT[m][j*128+i] = Q[j][i]
__device__ float g_table[4096 * 128];    // pathemb table for every position value

// Inter-block phase counters, 128B apart. Zero at load; reset each call by the
// last block through the exit counter -> replay-safe.
__device__ volatile unsigned g_flags[3 * 32];  // [0]=c1 lu, [32]=c2 solve, [64]=exit

#define LU_PITCH 129
#define NBLOCKS  128
#define TBL_SMEM_FLOATS (2 * 16384 + 2 * 2048)   // 144 KB dynamic

__device__ __forceinline__ void poll_ge(int idx, unsigned tgt) {
    while (g_flags[idx] < tgt) {}
}

// ---------------------------------------------------------------------------
// Mega preproc kernel: rank-2 LU (blk 0-1) -> solve (blk 0-15) -> table (all).
// 128 blocks, 1/SM (144KB smem), all resident -> spin-sync deadlock-free.
// ---------------------------------------------------------------------------
__global__ __launch_bounds__(512, 1) void mega_kernel(const float* __restrict__ X,
                                                      const float* __restrict__ identity) {
    extern __shared__ float sm[];
    // rank-2 LU staging (double-buffered): two pivot columns + two pivot rows
    __shared__ float C0[2][128], C1[2][128], R0[2][128], R1[2][128];
    __shared__ int   pv[2][16];

    const int blk  = blockIdx.x;
    const int t    = threadIdx.x;
    const int tr   = t & 31;          // lane
    const int w    = t >> 5;          // warp id (0..15): owns columns 8w..8w+7
    const unsigned FULL = 0xffffffffu;

    // ====================== Phase 1: rank-2 LU (64 steps) ===================
    if (blk < 2) {
        const int m = blk;
        const float* Xm = X + m * 128 * 128;
        float* Xs = sm;                                  // 128*129

        for (int idx = t; idx < 128 * 128; idx += 512)
            Xs[(idx >> 7) * LU_PITCH + (idx & 127)] = Xm[idx];
        __syncthreads();

        // init M = I - 0.5*(tril(X) - tril(X)^T)
        float reg[4][8];
#pragma unroll
        for (int s = 0; s < 4; s++) {
            const int r = tr + 32 * s;
#pragma unroll
            for (int q = 0; q < 8; q++) {
                const int c = 8 * w + q;
                float a = (r > c) ? Xs[r * LU_PITCH + c]
                        : ((r < c) ? -Xs[c * LU_PITCH + r] : 0.0f);
                reg[s][q] = ((r == c) ? 1.0f : 0.0f) - 0.5f * a;
            }
        }

        // stage pair 0 (cols 0,1 / rows 0,1) into buffer 0
        if (w == 0) {
#pragma unroll
            for (int s = 0; s < 4; s++) {
                C0[0][tr + 32 * s] = reg[s][0];
                C1[0][tr + 32 * s] = reg[s][1];
            }
        }
        if (tr == 0) {
#pragma unroll
            for (int q = 0; q < 8; q++) R0[0][8 * w + q] = reg[0][q];
        }
        if (tr == 1) {
#pragma unroll
            for (int q = 0; q < 8; q++) R1[0][8 * w + q] = reg[0][q];
        }

        for (int kp = 0; kp < 64; kp++) {
            __syncthreads();
            const int p = kp & 1;
            const int k = 2 * kp;

            if (8 * w + 7 >= k) {                        // warp-uniform dead skip
                // 2x2 pivot scalars (rows k,k+1 staged raw post-update)
                const float a = R0[p][k];
                const float b = R0[p][k + 1];
                const float c = R1[p][k];
                const float d = R1[p][k + 1];
                const float inva  = 1.0f / a;
                const float tmul  = c * inva;            // L[k+1,k]
                const float td    = d - tmul * b;        // U[k+1,k+1]
                const float invtd = 1.0f / td;

                float u1[8], u2[8];
#pragma unroll
                for (int q = 0; q < 8; q++) {
                    u1[q] = R0[p][8 * w + q];
                    u2[q] = R1[p][8 * w + q] - tmul * u1[q];   // effective U_{k+1}
                }

#pragma unroll
                for (int s = 0; s < 4; s++) {
                    const int r = tr + 32 * s;
                    if (r > k + 1) {
                        const float cl0 = C0[p][r];
                        const float cl1 = C1[p][r];
                        const float l1 = cl0 * inva;
                        const float l2 = (cl1 - l1 * b) * invtd;
#pragma unroll
                        for (int q = 0; q < 8; q++) {
                            const int cc = 8 * w + q;
                            if (cc > k + 1)       reg[s][q] -= l1 * u1[q] + l2 * u2[q];
                            else if (cc == k)     reg[s][q]  = l1;
                            else if (cc == k + 1) reg[s][q]  = l2;
                        }
                    } else if (r == k + 1) {
                        // this row becomes U_{k+1}: row -= t*U_k ; L[k+1,k]=t
#pragma unroll
                        for (int q = 0; q < 8; q++) {
                            const int cc = 8 * w + q;
                            if (cc >= k + 1)  reg[s][q] -= tmul * u1[q];
                            else if (cc == k) reg[s][q]  = tmul;
                        }
                    }
                }

                // stage next pair (cols/rows k+2,k+3) from post-update registers
                if (kp < 63) {
                    const int kn = k + 2;
                    if (w == (kn >> 3)) {                // column owner warp
                        const int qn = kn & 7;           // even: 0,2,4,6
#pragma unroll
                        for (int s = 0; s < 4; s++) {
                            float v0 = reg[s][0], v1 = reg[s][1];
#pragma unroll
                            for (int qq = 2; qq < 8; qq += 2) {
                                if (qq == qn) { v0 = reg[s][qq]; v1 = reg[s][qq + 1]; }
                            }
                            C0[p ^ 1][tr + 32 * s] = v0;
                            C1[p ^ 1][tr + 32 * s] = v1;
                        }
                    }
                    if (tr == (kn & 31)) {               // row kn owner lane
                        const int sn = kn >> 5;
#pragma unroll
                        for (int q = 0; q < 8; q++) {
                            float v = reg[0][q];
#pragma unroll
                            for (int ss = 1; ss < 4; ss++)
                                if (ss == sn) v = reg[ss][q];
                            R0[p ^ 1][8 * w + q] = v;
                        }
                    }
                    if (tr == ((kn + 1) & 31)) {         // row kn+1 owner lane
                        const int sn = (kn + 1) >> 5;
#pragma unroll
                        for (int q = 0; q < 8; q++) {
                            float v = reg[0][q];
#pragma unroll
                            for (int ss = 1; ss < 4; ss++)
                                if (ss == sn) v = reg[ss][q];
                            R1[p ^ 1][8 * w + q] = v;
                        }
                    }
                }
            }
        }
        __syncthreads();
#pragma unroll
        for (int s = 0; s < 4; s++) {
            const int r = tr + 32 * s;
#pragma unroll
            for (int q = 0; q < 8; q++)
                Xs[r * LU_PITCH + 8 * w + q] = reg[s][q];
        }
        __syncthreads();
        for (int idx = t; idx < 128 * 128; idx += 512)
            g_LU[m][idx] = Xs[(idx >> 7) * LU_PITCH + (idx & 127)];
        __syncthreads();
        __threadfence();
        if (t == 0) atomicAdd((unsigned*)&g_flags[0], 1u);      // c1++
    }

    // =========================== Phase 2: solve =============================
    if (blk < 16) {
        if (t == 0) poll_ge(0, 2u);
        __syncthreads();
        __threadfence();

        const int m = blk >> 3;
        const int j = ((blk & 7) << 4) + w;              // 16 RHS per block
        const float* Xm  = X + m * 128 * 128;
        const float* LUg = g_LU[m];
        float* LUs   = sm;                               // 128*129
        float* rdiag = sm + 128 * LU_PITCH;              // 128

        for (int idx = t; idx < 128 * 128; idx += 512)
            LUs[(idx >> 7) * LU_PITCH + (idx & 127)] = LUg[idx];
        if (t < 128) rdiag[t] = 1.0f / LUg[t * 128 + t];
        __syncthreads();

        const int lane = tr;
        float y0, y1, y2, y3;
        {
            const int i0 = lane, i1 = lane + 32, i2 = lane + 64, i3 = lane + 96;
            float a0 = (i0 > j) ? Xm[i0 * 128 + j] : ((i0 < j) ? -Xm[j * 128 + i0] : 0.0f);
            float a1 = (i1 > j) ? Xm[i1 * 128 + j] : ((i1 < j) ? -Xm[j * 128 + i1] : 0.0f);
            float a2 = (i2 > j) ? Xm[i2 * 128 + j] : ((i2 < j) ? -Xm[j * 128 + i2] : 0.0f);
            float a3 = (i3 > j) ? Xm[i3 * 128 + j] : ((i3 < j) ? -Xm[j * 128 + i3] : 0.0f);
            y0 = ((i0 == j) ? 1.0f : 0.0f) + 0.5f * a0;
            y1 = ((i1 == j) ? 1.0f : 0.0f) + 0.5f * a1;
            y2 = ((i2 == j) ? 1.0f : 0.0f) + 0.5f * a2;
            y3 = ((i3 == j) ? 1.0f : 0.0f) + 0.5f * a3;
        }

        // forward: L z = r (unit lower)
#pragma unroll 4
        for (int kk = 0; kk < 32; kk++) {
            const float yk = __shfl_sync(FULL, y0, kk);
            const float* col = LUs + kk;
            if (lane > kk) y0 -= col[lane * LU_PITCH] * yk;
            y1 -= col[(lane + 32) * LU_PITCH] * yk;
            y2 -= col[(lane + 64) * LU_PITCH] * yk;
            y3 -= col[(lane + 96) * LU_PITCH] * yk;
        }
#pragma unroll 4
        for (int kk = 0; kk < 32; kk++) {
            const float yk = __shfl_sync(FULL, y1, kk);
            const float* col = LUs + 32 + kk;
            if (lane > kk) y1 -= col[(lane + 32) * LU_PITCH] * yk;
            y2 -= col[(lane + 64) * LU_PITCH] * yk;
            y3 -= col[(lane + 96) * LU_PITCH] * yk;
        }
#pragma unroll 4
        for (int kk = 0; kk < 32; kk++) {
            const float yk = __shfl_sync(FULL, y2, kk);
            const float* col = LUs + 64 + kk;
            if (lane > kk) y2 -= col[(lane + 64) * LU_PITCH] * yk;
            y3 -= col[(lane + 96) * LU_PITCH] * yk;
        }
#pragma unroll 4
        for (int kk = 0; kk < 31; kk++) {
            const float yk = __shfl_sync(FULL, y3, kk);
            if (lane > kk) y3 -= LUs[(lane + 96) * LU_PITCH + 96 + kk] * yk;
        }
        // backward: U q = z
#pragma unroll 4
        for (int kk = 31; kk >= 0; kk--) {
            const int k = 96 + kk;
            const float yk = __shfl_sync(FULL, y3, kk) * rdiag[k];
            if (lane == kk) y3 = yk;
            else if (lane < kk) y3 -= LUs[(lane + 96) * LU_PITCH + k] * yk;
            y0 -= LUs[lane * LU_PITCH + k] * yk;
            y1 -= LUs[(lane + 32) * LU_PITCH + k] * yk;
            y2 -= LUs[(lane + 64) * LU_PITCH + k] * yk;
        }
#pragma unroll 4
        for (int kk = 31; kk >= 0; kk--) {
            const int k = 64 + kk;
            const float yk = __shfl_sync(FULL, y2, kk) * rdiag[k];
            if (lane == kk) y2 = yk;
            else if (lane < kk) y2 -= LUs[(lane + 64) * LU_PITCH + k] * yk;
            y0 -= LUs[lane * LU_PITCH + k] * yk;
            y1 -= LUs[(lane + 32) * LU_PITCH + k] * yk;
        }
#pragma unroll 4
        for (int kk = 31; kk >= 0; kk--) {
            const int k = 32 + kk;
            const float yk = __shfl_sync(FULL, y1, kk) * rdiag[k];
            if (lane == kk) y1 = yk;
            else if (lane < kk) y1 -= LUs[(lane + 32) * LU_PITCH + k] * yk;
            y0 -= LUs[lane * LU_PITCH + k] * yk;
        }
#pragma unroll 4
        for (int kk = 31; kk >= 0; kk--) {
            const float yk = __shfl_sync(FULL, y0, kk) * rdiag[kk];
            if (lane == kk) y0 = yk;
            else if (lane < kk) y0 -= LUs[lane * LU_PITCH + kk] * yk;
        }
        float* dst = g_QT[m] + j * 128 + lane;
        dst[0] = y0; dst[32] = y1; dst[64] = y2; dst[96] = y3;

        __syncthreads();
        __threadfence();
        if (t == 0) atomicAdd((unsigned*)&g_flags[32], 1u);     // c2++
    }

    // =========================== Phase 3: table =============================
    if (t == 0) poll_ge(32, 16u);
    __syncthreads();
    __threadfence();

    {
        float* Q0s  = sm;
        float* Q1s  = sm + 16384;
        float* bufA = sm + 32768;
        float* bufB = sm + 34816;
        const int g = blk;
        const int l = t >> 7;
        const int j = t & 127;

        {
            const float4* src = (const float4*)g_QT;
            float4* dst = (float4*)sm;
            for (int i = t; i < 8192; i += 512) dst[i] = src[i];
        }
        if (t < 128) bufA[j] = identity[j];
        if (g == 0 && t < 128) {
            g_table[0 + j]   = identity[j];
            g_table[128 + j] = identity[j];
        }
        __syncthreads();

        float* cur = bufA;
        float* nxt = bufB;
        for (int d = 0; d < 7; d++) {                    // root path: levels 2..8
            if (t < 128) {
                const int b = (g >> d) & 1;
                const float* Qp = b ? Q1s : Q0s;
                float a0 = 0.f, a1 = 0.f, a2 = 0.f, a3 = 0.f;
#pragma unroll
                for (int i = 0; i < 128; i += 4) {
                    const float4 vv = *(const float4*)(cur + i);
                    a0 += vv.x * Qp[(i + 0) * 128 + j];
                    a1 += vv.y * Qp[(i + 1) * 128 + j];
                    a2 += vv.z * Qp[(i + 2) * 128 + j];
                    a3 += vv.w * Qp[(i + 3) * 128 + j];
                }
                const float acc = (a0 + a1) + (a2 + a3);
                nxt[j] = acc;
                const int p = (g & ((2 << d) - 1)) | (2 << d);
                g_table[p * 128 + j] = acc;
            }
            __syncthreads();
            float* tmp = cur; cur = nxt; nxt = tmp;
        }
        if (t == 0) pv[0][0] = 128 + g;
        __syncthreads();

        int cnt = 1, msb = 128, sel = 0;
        for (int lvl = 0; lvl < 4; lvl++) {              // levels 9..12
            const int nch = cnt * 2;
            for (int cb = 0; cb < nch; cb += 4) {
                const int c = cb + l;
                if (c < nch) {
                    const int par = c >> 1;
                    const int b   = c & 1;
                    const int pc  = pv[sel][par] + (b + 1) * msb;
                    const float* Qp = b ? Q1s : Q0s;
                    const float* vp = cur + par * 128;
                    float a0 = 0.f, a1 = 0.f, a2 = 0.f, a3 = 0.f;
#pragma unroll
                    for (int i = 0; i < 128; i += 4) {
                        const float4 vv = *(const float4*)(vp + i);
                        a0 += vv.x * Qp[(i + 0) * 128 + j];
                        a1 += vv.y * Qp[(i + 1) * 128 + j];
                        a2 += vv.z * Qp[(i + 2) * 128 + j];
                        a3 += vv.w * Qp[(i + 3) * 128 + j];
                    }
                    const float acc = (a0 + a1) + (a2 + a3);
                    nxt[c * 128 + j] = acc;
                    g_table[pc * 128 + j] = acc;
                    if (j == 0) pv[sel ^ 1][c] = pc;
                }
            }
            __syncthreads();
            float* tmp = cur; cur = nxt; nxt = tmp;
            sel ^= 1; cnt = nch; msb <<= 1;
        }
    }

    // ============ exit counter + replay-safe flag reset =====================
    __syncthreads();
    __threadfence();
    if (t == 0) {
        if (atomicAdd((unsigned*)&g_flags[64], 1u) == NBLOCKS - 1) {
            g_flags[0]  = 0u;
            g_flags[32] = 0u;
            g_flags[64] = 0u;
            __threadfence();
        }
    }
}

// ---------------------------------------------------------------------------
// Kernel 2: final embedding assembly. One warp per token, float4 streaming
// stores. 128 MB write -> HBM-bound (known 24us).
// ---------------------------------------------------------------------------
__global__ __launch_bounds__(256) void out_kernel(const int* __restrict__ tt,
                                                  const int* __restrict__ tv,
                                                  const int* __restrict__ np,
                                                  const float* __restrict__ ew,
                                                  float* __restrict__ out) {
    const int warp = threadIdx.x >> 5;
    const int lane = threadIdx.x & 31;
    const int tok  = blockIdx.x * 8 + warp;      // < 131072

    const int ty  = tt[tok];
    const int val = tv[tok];
    const int pos = np[tok];

    const float4 pv4 = *(const float4*)(g_table + pos * 128 + lane * 4);

    float4 cv;
    if (ty == 4) {
        int idx = val < 0 ? 0 : (val > 4095 ? 4095 : val);
        cv = *(const float4*)(g_table + idx * 128 + lane * 4);
    } else if (ty == 1) {
        cv = *(const float4*)(ew + (val + 1) * 128 + lane * 4);
    } else if (ty == 2) {
        cv = *(const float4*)(ew + (val + 5) * 128 + lane * 4);
    } else if (ty == 0) {
        cv = *(const float4*)(ew + lane * 4);
    } else if (ty == 3 && val == -1) {
        cv = *(const float4*)(ew + 10 * 128 + lane * 4);
    } else {
        cv = make_float4(0.f, 0.f, 0.f, 0.f);
    }

    float* o = out + (size_t)tok * 256;
    __stcs((float4*)(o + lane * 4), cv);
    __stcs((float4*)(o + 128 + lane * 4), pv4);
}

// ---------------------------------------------------------------------------
extern "C" void kernel_launch(void* const* d_in, const int* in_sizes, int n_in,
                              void* d_out, int out_size) {
    const int*   tt    = (const int*)d_in[0];   // token_types   [32,4096]
    const int*   tv    = (const int*)d_in[1];   // token_values  [32,4096]
    const int*   np    = (const int*)d_in[2];   // node_positions[32,4096]
    const float* prim  = (const float*)d_in[3]; // primitives    [2,128,128]
    const float* ident = (const float*)d_in[4]; // identity      [1,128]
    const float* ew    = (const float*)d_in[5]; // embed_weight  [11,128]
    float* out = (float*)d_out;

    const int mega_smem = TBL_SMEM_FLOATS * (int)sizeof(float);   // 147456 B
    cudaFuncSetAttribute(mega_kernel, cudaFuncAttributeMaxDynamicSharedMemorySize, mega_smem);

    mega_kernel<<<NBLOCKS, 512, mega_smem>>>(prim, ident);
    out_kernel<<<16384, 256>>>(tt, tv, np, ew, out);
}